// round 7
// baseline (speedup 1.0000x reference)
#include <cuda_runtime.h>
#include <cuda_bf16.h>
#include <cstdint>
#include <math.h>

// simpleLSTM B=64 T=1024 I=512 H=1024 — v7: hoisted x-GEMM (k 256..511) +
// HMMA bf16-2split persistent recurrence (K=1280), asymmetric K-split groups
// so the grid barrier hides behind x-chunk compute / sibling-warp compute.

namespace {
constexpr int kB=64, kT=1024, kI=512, kH=1024;
constexpr int kNCTA=128, kNTHR=256;
constexpr int BLOB=8192;               // per-chunk A fragment blob (hi+lo)
// main kernel SMEM
constexpr int WHI=0;                   // 20 weight tiles x 4096B
constexpr int WLO=81920;
constexpr int ACC0=163840;             // [2 groups][64][37] f32
constexpr int ACCSTR=37;
constexpr int ACCSZ=64*ACCSTR*4;
constexpr int SMEMB=ACC0+2*ACCSZ;      // 182784
// xproj kernel SMEM
constexpr int BHI=0, BLO=65536, XSMEM=131072;
}

__device__ unsigned char g_xt[(size_t)kT*16*BLOB];   // x fragment blobs (16/t)
__device__ unsigned char g_ht[(size_t)2*32*BLOB];    // h blobs: 2 par x 32
__device__ float g_xp[(size_t)kT*128*64*32];         // X_proj partial (1GB)
__device__ int g_arr[kT];

__device__ __forceinline__ uint32_t smem_u32_of(const void* p) {
    uint32_t a;
    asm("{ .reg .u64 t0; cvta.to.shared.u64 t0, %1; cvt.u32.u64 %0, t0; }"
        : "=r"(a) : "l"(p));
    return a;
}
__device__ __forceinline__ uint32_t swz128(uint32_t o) { return o ^ ((o >> 3) & 0x70); }
__device__ __forceinline__ float sigf(float x) { return 1.0f / (1.0f + expf(-x)); }
__device__ __forceinline__ void spin_on(const int* p, uint32_t n) {
    uint32_t v;
    do {
        asm volatile("ld.acquire.gpu.global.u32 %0, [%1];" : "=r"(v) : "l"(p) : "memory");
    } while (v < n);
}

#define LDSM4(R, A) \
    asm volatile("ldmatrix.sync.aligned.m8n8.x4.shared.b16 {%0,%1,%2,%3}, [%4];" \
        : "=r"((R)[0]), "=r"((R)[1]), "=r"((R)[2]), "=r"((R)[3]) : "r"(A))

#define MMA16816(D, A, B0, B1) \
    asm volatile("mma.sync.aligned.m16n8k16.row.col.f32.bf16.bf16.f32 " \
        "{%0,%1,%2,%3}, {%4,%5,%6,%7}, {%8,%9}, {%0,%1,%2,%3};" \
        : "+f"((D)[0]), "+f"((D)[1]), "+f"((D)[2]), "+f"((D)[3]) \
        : "r"((A)[0]), "r"((A)[1]), "r"((A)[2]), "r"((A)[3]), "r"(B0), "r"(B1))

__global__ void lstm7_init() {
    int i = blockIdx.x * blockDim.x + threadIdx.x;
    if (i < kT) g_arr[i] = 0;
    if (i < (int)(sizeof(g_ht) / 16))
        ((uint4*)g_ht)[i] = make_uint4(0u, 0u, 0u, 0u);
}

// x fragment blobs: block = t*16 + c (c = k32-chunk of x). Layout per (s,ks):
// hi: s*2048 + ks*512 + lane*16 + r*4 ; lo at +1024.
__global__ void __launch_bounds__(128) lstm7_xsplit(const float* __restrict__ x) {
    __shared__ float xt[64 * 32];
    const int bx = blockIdx.x, t = bx >> 4, c = bx & 15, tid = threadIdx.x;
    #pragma unroll
    for (int v = 0; v < 4; ++v) {
        int idx = tid + v * 128;
        int b = idx >> 3, ko = (idx & 7) * 4;
        float4 f = *(const float4*)(x + ((size_t)b * kT + t) * kI + c * 32 + ko);
        *(float4*)(xt + b * 32 + ko) = f;
    }
    __syncthreads();
    const int s = tid >> 5, ks = (tid >> 4) & 1, l2 = tid & 15;
    unsigned char* base = g_xt + (size_t)bx * BLOB + s * 2048 + ks * 512;
    #pragma unroll
    for (int dl = 0; dl < 2; ++dl) {
        int l = l2 * 2 + dl;
        uint32_t hi[4], lo[4];
        #pragma unroll
        for (int r = 0; r < 4; ++r) {
            int row = s * 16 + (l >> 2) + 8 * (r & 1);
            int col = ks * 16 + 8 * (r >> 1) + (l & 3) * 2;
            float f0 = xt[row * 32 + col], f1 = xt[row * 32 + col + 1];
            __nv_bfloat16 h0 = __float2bfloat16(f0);
            __nv_bfloat16 h1 = __float2bfloat16(f1);
            __nv_bfloat162 hp; hp.x = h0; hp.y = h1;
            __nv_bfloat162 lp = __floats2bfloat162_rn(
                f0 - __bfloat162float(h0), f1 - __bfloat162float(h1));
            hi[r] = *(uint32_t*)&hp;
            lo[r] = *(uint32_t*)&lp;
        }
        *(uint4*)(base + l * 16)        = make_uint4(hi[0], hi[1], hi[2], hi[3]);
        *(uint4*)(base + 1024 + l * 16) = make_uint4(lo[0], lo[1], lo[2], lo[3]);
    }
}

__device__ __forceinline__ void lda(uint4* a, const unsigned char* p, int lane) {
    a[0] = __ldcg((const uint4*)(p + lane * 16));
    a[1] = __ldcg((const uint4*)(p + 512 + lane * 16));
    a[2] = __ldcg((const uint4*)(p + 1024 + lane * 16));
    a[3] = __ldcg((const uint4*)(p + 1536 + lane * 16));
}

// ---------------- upfront x-projection GEMM (k 256..511) ----------------
// grid = 32 tpg x 32 ns; block = 256 thr; each block: 16 t-pairs, N=128, K=256.
__global__ void __launch_bounds__(256) lstm7_xproj(
    const float* __restrict__ Wf, const float* __restrict__ Wi,
    const float* __restrict__ Wo, const float* __restrict__ Wc)
{
    extern __shared__ unsigned char smem[];
    const uint32_t sbb = smem_u32_of(smem);
    const int tid = threadIdx.x, lane = tid & 31, w = tid >> 5;
    const int ns = blockIdx.x & 31, tpg = blockIdx.x >> 5;
    const int ms = w >> 1, nh = w & 1;     // m32 slice, n64 half

    // stage B: rows n=0..127 (gcol = ns*128+n), k 256..511, hi/lo SW128 tiles
    {
        const float* const Wp[4] = {Wf, Wi, Wo, Wc};
        const int r = tid >> 1, kh = (tid & 1) * 128;
        const int gcol = ns * 128 + r;
        const float* src = Wp[r & 3] + (size_t)((gcol >> 5) * 8 + ((r >> 2) & 7)) * 1536 + 256;
        #pragma unroll 8
        for (int kk = 0; kk < 64; ++kk) {
            int ko = kh + kk * 2;
            float f0 = __ldg(src + ko), f1 = __ldg(src + ko + 1);
            __nv_bfloat16 h0 = __float2bfloat16(f0);
            __nv_bfloat16 h1 = __float2bfloat16(f1);
            __nv_bfloat162 hp; hp.x = h0; hp.y = h1;
            __nv_bfloat162 lp = __floats2bfloat162_rn(
                f0 - __bfloat162float(h0), f1 - __bfloat162float(h1));
            uint32_t off = swz128((uint32_t)((ko >> 6) * 16384 + (r << 7) + ((ko & 63) << 1)));
            *(uint32_t*)(smem + BHI + off) = *(uint32_t*)&hp;
            *(uint32_t*)(smem + BLO + off) = *(uint32_t*)&lp;
        }
    }
    __syncthreads();

    const int rowB = ((lane >> 4) << 3) + (lane & 7);
    const int bXor = rowB & 7, bCB = (lane >> 3) & 1;

    for (int tp2 = 0; tp2 < 16; ++tp2) {
        const int tp = tpg * 16 + tp2;
        const int tA = 2 * tp + (ms >> 1);
        const int s0 = (ms & 1) * 2;
        float acc[2][8][4];
        #pragma unroll
        for (int mt = 0; mt < 2; ++mt)
            #pragma unroll
            for (int nt = 0; nt < 8; ++nt)
                #pragma unroll
                for (int e = 0; e < 4; ++e) acc[mt][nt][e] = 0.0f;

        uint4 ab[2][2][4];
        {
            const unsigned char* bp = g_xt + (((size_t)tA * 16 + 8) << 13);
            lda(ab[0][0], bp + s0 * 2048, lane);
            lda(ab[0][1], bp + (s0 + 1) * 2048, lane);
        }
        #pragma unroll 2
        for (int kc = 0; kc < 8; ++kc) {
            if (kc + 1 < 8) {
                const unsigned char* bp = g_xt + (((size_t)tA * 16 + 9 + kc) << 13);
                lda(ab[(kc + 1) & 1][0], bp + s0 * 2048, lane);
                lda(ab[(kc + 1) & 1][1], bp + (s0 + 1) * 2048, lane);
            }
            #pragma unroll
            for (int ks = 0; ks < 2; ++ks) {
                uint32_t cb = (uint32_t)(((2 * ((kc & 1) * 2 + ks) + bCB) ^ bXor) << 4);
                uint32_t tbase = sbb + (uint32_t)((kc >> 1) * 16384 + (nh * 64 + rowB) * 128) + cb;
                const uint32_t* ah0 = (const uint32_t*)&ab[kc & 1][0][ks];
                const uint32_t* al0 = (const uint32_t*)&ab[kc & 1][0][2 + ks];
                const uint32_t* ah1 = (const uint32_t*)&ab[kc & 1][1][ks];
                const uint32_t* al1 = (const uint32_t*)&ab[kc & 1][1][2 + ks];
                #pragma unroll
                for (int ng = 0; ng < 4; ++ng) {
                    uint32_t bh[4], bl[4];
                    LDSM4(bh, tbase + (uint32_t)(ng * 16 * 128));
                    LDSM4(bl, tbase + (uint32_t)(BLO + ng * 16 * 128));
                    MMA16816(acc[0][2*ng],   ah0, bh[0], bh[1]);
                    MMA16816(acc[0][2*ng+1], ah0, bh[2], bh[3]);
                    MMA16816(acc[1][2*ng],   ah1, bh[0], bh[1]);
                    MMA16816(acc[1][2*ng+1], ah1, bh[2], bh[3]);
                    MMA16816(acc[0][2*ng],   ah0, bl[0], bl[1]);
                    MMA16816(acc[0][2*ng+1], ah0, bl[2], bl[3]);
                    MMA16816(acc[1][2*ng],   ah1, bl[0], bl[1]);
                    MMA16816(acc[1][2*ng+1], ah1, bl[2], bl[3]);
                    MMA16816(acc[0][2*ng],   al0, bh[0], bh[1]);
                    MMA16816(acc[0][2*ng+1], al0, bh[2], bh[3]);
                    MMA16816(acc[1][2*ng],   al1, bh[0], bh[1]);
                    MMA16816(acc[1][2*ng+1], al1, bh[2], bh[3]);
                }
            }
        }
        // store to g_xp[t][cta][b][n32]
        const int b0 = (ms & 1) * 32 + (lane >> 2);
        #pragma unroll
        for (int mt = 0; mt < 2; ++mt) {
            #pragma unroll
            for (int nt = 0; nt < 8; ++nt) {
                int nl = nh * 64 + nt * 8 + (lane & 3) * 2;
                int gcol = ns * 128 + nl;
                size_t base = ((size_t)tA * 128 + (gcol >> 5)) * 64;
                int n32 = gcol & 31;
                *(float2*)(g_xp + (base + b0 + mt * 16) * 32 + n32) =
                    make_float2(acc[mt][nt][0], acc[mt][nt][1]);
                *(float2*)(g_xp + (base + b0 + mt * 16 + 8) * 32 + n32) =
                    make_float2(acc[mt][nt][2], acc[mt][nt][3]);
            }
        }
    }
}

// ---------------- recurrent persistent kernel ----------------
__device__ __forceinline__ const unsigned char* ablob7(int t, int c, int s) {
    if (c < 8) return g_xt + (((size_t)(t * 16 + c)) << 13) + s * 2048;
    return g_ht + (((size_t)((t & 1) * 32 + (c - 8))) << 13) + s * 2048;
}

__global__ void __launch_bounds__(kNTHR, 1) lstm7_kernel(
    const float* __restrict__ Wf, const float* __restrict__ bf,
    const float* __restrict__ Wi, const float* __restrict__ bi,
    const float* __restrict__ Wo, const float* __restrict__ bo,
    const float* __restrict__ Wc, const float* __restrict__ bc,
    float* __restrict__ out)
{
    extern __shared__ unsigned char smem[];
    const uint32_t sb = smem_u32_of(smem);
    const int tid = threadIdx.x, lane = tid & 31, w = tid >> 5;
    const int g = w >> 2, s = w & 3;      // k-group (asym), m-slice
    const int cta = blockIdx.x, j0 = cta * 8;

    // stage recurrent weights: k 0..255 (x) + cols 512..1535 (h) = 20 tiles
    {
        const float* const Wp[4] = {Wf, Wi, Wo, Wc};
        for (int r = 0; r < 32; ++r) {
            const float* src = Wp[r & 3] + (size_t)(j0 + (r >> 2)) * 1536;
            for (int kp = tid; kp < 640; kp += kNTHR) {
                int kr = kp * 2;
                int kc0 = kr < 256 ? kr : kr + 256;
                float f0 = __ldg(src + kc0), f1 = __ldg(src + kc0 + 1);
                __nv_bfloat16 h0 = __float2bfloat16(f0);
                __nv_bfloat16 h1 = __float2bfloat16(f1);
                __nv_bfloat162 hp; hp.x = h0; hp.y = h1;
                __nv_bfloat162 lp = __floats2bfloat162_rn(
                    f0 - __bfloat162float(h0), f1 - __bfloat162float(h1));
                uint32_t off = swz128((uint32_t)((kr >> 6) * 4096 + (r << 7) + ((kr & 63) << 1)));
                *(uint32_t*)(smem + WHI + off) = *(uint32_t*)&hp;
                *(uint32_t*)(smem + WLO + off) = *(uint32_t*)&lp;
            }
        }
    }

    const int rowB = ((lane >> 4) << 3) + (lane & 7);
    const uint32_t bRow = (uint32_t)rowB * 128;
    const int bXor = rowB & 7, bCB = (lane >> 3) & 1;

    const int m0 = s * 16;
    const int mA = m0 + (lane >> 2), cA = (lane & 3) * 2;
    float* abuf = (float*)(smem + ACC0 + g * ACCSZ);

    const int eb = tid & 63, ej = tid >> 6;
    float bb[2][4];
    {
        const float* const Bp[4] = {bf, bi, bo, bc};
        #pragma unroll
        for (int u = 0; u < 2; ++u)
            #pragma unroll
            for (int g2 = 0; g2 < 4; ++g2)
                bb[u][g2] = __ldg(Bp[g2] + j0 + ej * 2 + u);
    }
    // h fragment write address pieces
    const int jlh = ej * 2;
    const int colh = (j0 & 31) + jlh;
    const int s2 = eb >> 4, ri16 = eb & 15;
    const int lane2 = (ri16 & 7) * 4 + ((colh & 7) >> 1);
    const int r2 = (ri16 >> 3) + 2 * ((colh & 15) >> 3);
    const int ks2 = (colh >> 4) & 1;
    const size_t hoff = (size_t)s2 * 2048 + ks2 * 512 + lane2 * 16 + r2 * 4;
    const size_t hcsel = (size_t)(j0 >> 5) << 13;

    float cs[2] = {0.f, 0.f};
    __syncthreads();

    uint4 ap[4][4];
    lda(ap[0], ablob7(0, g * 20 + 0, s), lane);
    lda(ap[1], ablob7(0, g * 20 + 1, s), lane);
    lda(ap[2], ablob7(0, g * 20 + 2, s), lane);

    for (int t = 0; t < kT; ++t) {
        // prefetch this step's X_proj slice
        const float* xpp = g_xp + (((size_t)t * 128 + cta) * 64 + eb) * 32 + ej * 8;
        float4 xpa = __ldcg((const float4*)xpp);
        float4 xpb = __ldcg((const float4*)(xpp + 4));

        float acc[4][4];
        #pragma unroll
        for (int nt = 0; nt < 4; ++nt)
            #pragma unroll
            for (int e = 0; e < 4; ++e) acc[nt][e] = 0.0f;

        #pragma unroll 4
        for (int i = 0; i < 20; ++i) {
            if (t > 0) {
                if (g == 0 && i == 5) spin_on(g_arr + (t - 1), kNCTA);
                if (g == 1 && i == 0) {
                    spin_on(g_arr + (t - 1), kNCTA);
                    lda(ap[0], ablob7(t, 20, s), lane);
                    lda(ap[1], ablob7(t, 21, s), lane);
                    lda(ap[2], ablob7(t, 22, s), lane);
                }
            }
            const int c = g * 20 + i;
            const uint32_t bhB = sb + WHI + (uint32_t)(c >> 1) * 4096;
            const int ksg0 = (c & 1) * 2;
            #pragma unroll
            for (int ks = 0; ks < 2; ++ks) {
                uint32_t bh0[4], bh1[4], bl0[4], bl1[4];
                uint32_t cb = (uint32_t)(((2 * (ksg0 + ks) + bCB) ^ bXor) << 4);
                LDSM4(bh0, bhB + bRow + cb);
                LDSM4(bh1, bhB + bRow + cb + 2048);
                LDSM4(bl0, bhB + (WLO - WHI) + bRow + cb);
                LDSM4(bl1, bhB + (WLO - WHI) + bRow + cb + 2048);
                const uint32_t* ah = (const uint32_t*)&ap[i & 3][ks];
                const uint32_t* al = (const uint32_t*)&ap[i & 3][2 + ks];
                MMA16816(acc[0], ah, bh0[0], bh0[1]);
                MMA16816(acc[1], ah, bh0[2], bh0[3]);
                MMA16816(acc[2], ah, bh1[0], bh1[1]);
                MMA16816(acc[3], ah, bh1[2], bh1[3]);
                MMA16816(acc[0], ah, bl0[0], bl0[1]);
                MMA16816(acc[1], ah, bl0[2], bl0[3]);
                MMA16816(acc[2], ah, bl1[0], bl1[1]);
                MMA16816(acc[3], ah, bl1[2], bl1[3]);
                MMA16816(acc[0], al, bh0[0], bh0[1]);
                MMA16816(acc[1], al, bh0[2], bh0[3]);
                MMA16816(acc[2], al, bh1[0], bh1[1]);
                MMA16816(acc[3], al, bh1[2], bh1[3]);
            }
            if (i < 17)
                lda(ap[(i + 3) & 3], ablob7(t, c + 3, s), lane);
        }

        // g0 prefetches next step's x chunks (immutable) during epilogue
        if (g == 0 && t + 1 < kT) {
            lda(ap[0], ablob7(t + 1, 0, s), lane);
            lda(ap[1], ablob7(t + 1, 1, s), lane);
            lda(ap[2], ablob7(t + 1, 2, s), lane);
        }

        // stage partial D
        #pragma unroll
        for (int nt = 0; nt < 4; ++nt) {
            abuf[mA * ACCSTR + nt * 8 + cA]           = acc[nt][0];
            abuf[mA * ACCSTR + nt * 8 + cA + 1]       = acc[nt][1];
            abuf[(mA + 8) * ACCSTR + nt * 8 + cA]     = acc[nt][2];
            abuf[(mA + 8) * ACCSTR + nt * 8 + cA + 1] = acc[nt][3];
        }
        __syncthreads();

        // epilogue
        {
            const float* a0 = (const float*)(smem + ACC0);
            const float* a1 = (const float*)(smem + ACC0 + ACCSZ);
            const float* xp4[2] = {&xpa.x, &xpb.x};
            float hv[2];
            #pragma unroll
            for (int u = 0; u < 2; ++u) {
                int n = (ej * 2 + u) * 4;
                float sf = a0[eb*ACCSTR+n+0] + a1[eb*ACCSTR+n+0] + xp4[u][0] + bb[u][0];
                float si = a0[eb*ACCSTR+n+1] + a1[eb*ACCSTR+n+1] + xp4[u][1] + bb[u][1];
                float so = a0[eb*ACCSTR+n+2] + a1[eb*ACCSTR+n+2] + xp4[u][2] + bb[u][2];
                float sg = a0[eb*ACCSTR+n+3] + a1[eb*ACCSTR+n+3] + xp4[u][3] + bb[u][3];
                float f = sigf(sf), ii = sigf(si), o = sigf(so), gg = tanhf(sg);
                float cn = f * cs[u] + ii * gg;
                cs[u] = cn;
                hv[u] = o * tanhf(cn);
            }
            if (t < kT - 1) {
                __nv_bfloat16 h0 = __float2bfloat16(hv[0]);
                __nv_bfloat16 h1 = __float2bfloat16(hv[1]);
                __nv_bfloat162 hp; hp.x = h0; hp.y = h1;
                __nv_bfloat162 lp = __floats2bfloat162_rn(
                    hv[0] - __bfloat162float(h0), hv[1] - __bfloat162float(h1));
                unsigned char* dst = g_ht + ((size_t)(((t & 1) ^ 1) * 32) << 13)
                                   + hcsel + hoff;
                *(uint32_t*)dst          = *(uint32_t*)&hp;
                *(uint32_t*)(dst + 1024) = *(uint32_t*)&lp;
                __threadfence();
            } else {
                #pragma unroll
                for (int u = 0; u < 2; ++u) {
                    out[eb * kH + j0 + ej * 2 + u]           = hv[u];
                    out[kB * kH + eb * kH + j0 + ej * 2 + u] = cs[u];
                }
            }
        }
        __syncthreads();
        if (t < kT - 1 && tid == 0) atomicAdd(g_arr + t, 1);
    }
}

extern "C" void kernel_launch(void* const* d_in, const int* in_sizes, int n_in,
                              void* d_out, int out_size)
{
    (void)in_sizes; (void)n_in; (void)out_size;
    const float* x  = (const float*)d_in[0];
    const float* Wf = (const float*)d_in[1];
    const float* bf = (const float*)d_in[2];
    const float* Wi = (const float*)d_in[3];
    const float* bi = (const float*)d_in[4];
    const float* Wo = (const float*)d_in[5];
    const float* bo = (const float*)d_in[6];
    const float* Wc = (const float*)d_in[7];
    const float* bc = (const float*)d_in[8];
    float* out = (float*)d_out;

    cudaFuncSetAttribute(lstm7_kernel,
                         cudaFuncAttributeMaxDynamicSharedMemorySize, SMEMB);
    cudaFuncSetAttribute(lstm7_xproj,
                         cudaFuncAttributeMaxDynamicSharedMemorySize, XSMEM);
    lstm7_init<<<256, 256>>>();
    lstm7_xsplit<<<kT * 16, 128>>>(x);
    lstm7_xproj<<<1024, 256, XSMEM>>>(Wf, Wi, Wo, Wc);
    lstm7_kernel<<<kNCTA, kNTHR, SMEMB>>>(Wf, bf, Wi, bi, Wo, bo, Wc, bc, out);
}

// round 8
// speedup vs baseline: 1.2879x; 1.2879x over previous
#include <cuda_runtime.h>
#include <cuda_bf16.h>
#include <cstdint>
#include <math.h>

// simpleLSTM B=64 T=1024 I=512 H=1024 — v8: HMMA bf16-2split persistent kernel,
// 16 warps (4 M-slices x 4 K-groups), A global->register 3-buffer prefetch,
// per-warp JIT grid barrier, 4-buffer SMEM accumulator reduction.

namespace {
constexpr int kB=64, kT=1024, kI=512, kH=1024;
constexpr int kNCTA=128, kNTHR=512;
constexpr int BLOB=8192;               // per-chunk A fragment blob (hi+lo)
constexpr int WHI=0;                   // 24 weight tiles x 4096B
constexpr int WLO=98304;
constexpr int ACC0=196608;             // [4 k-groups][64][34] f32
constexpr int ACCSTR=34;
constexpr int ACCSZ=64*ACCSTR*4;       // 8704
constexpr int SMEMB=ACC0+4*ACCSZ;      // 231424 (<= 232448 max dyn)
}

__device__ unsigned char g_xt[(size_t)kT*16*BLOB];   // x fragment blobs
__device__ unsigned char g_ht[(size_t)2*32*BLOB];    // h blobs: 2 par x 32
__device__ int g_arr[kT];

__device__ __forceinline__ uint32_t smem_u32_of(const void* p) {
    uint32_t a;
    asm("{ .reg .u64 t0; cvta.to.shared.u64 t0, %1; cvt.u32.u64 %0, t0; }"
        : "=r"(a) : "l"(p));
    return a;
}
__device__ __forceinline__ uint32_t swz128(uint32_t o) { return o ^ ((o >> 3) & 0x70); }
__device__ __forceinline__ float sigf(float x) { return 1.0f / (1.0f + expf(-x)); }
__device__ __forceinline__ void spin_on(const int* p, uint32_t n) {
    uint32_t v;
    do {
        asm volatile("ld.acquire.gpu.global.u32 %0, [%1];" : "=r"(v) : "l"(p) : "memory");
    } while (v < n);
}

#define LDSM4(R, A) \
    asm volatile("ldmatrix.sync.aligned.m8n8.x4.shared.b16 {%0,%1,%2,%3}, [%4];" \
        : "=r"((R)[0]), "=r"((R)[1]), "=r"((R)[2]), "=r"((R)[3]) : "r"(A))

#define MMA16816(D, A, B0, B1) \
    asm volatile("mma.sync.aligned.m16n8k16.row.col.f32.bf16.bf16.f32 " \
        "{%0,%1,%2,%3}, {%4,%5,%6,%7}, {%8,%9}, {%0,%1,%2,%3};" \
        : "+f"((D)[0]), "+f"((D)[1]), "+f"((D)[2]), "+f"((D)[3]) \
        : "r"((A)[0]), "r"((A)[1]), "r"((A)[2]), "r"((A)[3]), "r"(B0), "r"(B1))

__global__ void lstm8_init() {
    int i = blockIdx.x * blockDim.x + threadIdx.x;
    if (i < kT) g_arr[i] = 0;
    if (i < (int)(sizeof(g_ht) / 16))
        ((uint4*)g_ht)[i] = make_uint4(0u, 0u, 0u, 0u);
}

// x fragment blobs: block = t*16 + c. Layout per (s,ks):
// hi: s*2048 + ks*512 + lane*16 + r*4 ; lo at +1024.
// Frag elem (lane,r,e): row = s*16+(lane>>2)+8*(r&1), col = ks*16+8*(r>>1)+(lane&3)*2+e.
__global__ void __launch_bounds__(128) lstm8_xsplit(const float* __restrict__ x) {
    __shared__ float xt[64 * 32];
    const int bx = blockIdx.x, t = bx >> 4, c = bx & 15, tid = threadIdx.x;
    #pragma unroll
    for (int v = 0; v < 4; ++v) {
        int idx = tid + v * 128;
        int b = idx >> 3, ko = (idx & 7) * 4;
        float4 f = *(const float4*)(x + ((size_t)b * kT + t) * kI + c * 32 + ko);
        *(float4*)(xt + b * 32 + ko) = f;
    }
    __syncthreads();
    const int s = tid >> 5, ks = (tid >> 4) & 1, l2 = tid & 15;
    unsigned char* base = g_xt + (size_t)bx * BLOB + s * 2048 + ks * 512;
    #pragma unroll
    for (int dl = 0; dl < 2; ++dl) {
        int l = l2 * 2 + dl;
        uint32_t hi[4], lo[4];
        #pragma unroll
        for (int r = 0; r < 4; ++r) {
            int row = s * 16 + (l >> 2) + 8 * (r & 1);
            int col = ks * 16 + 8 * (r >> 1) + (l & 3) * 2;
            float f0 = xt[row * 32 + col], f1 = xt[row * 32 + col + 1];
            __nv_bfloat16 h0 = __float2bfloat16(f0);
            __nv_bfloat16 h1 = __float2bfloat16(f1);
            __nv_bfloat162 hp; hp.x = h0; hp.y = h1;
            __nv_bfloat162 lp = __floats2bfloat162_rn(
                f0 - __bfloat162float(h0), f1 - __bfloat162float(h1));
            hi[r] = *(uint32_t*)&hp;
            lo[r] = *(uint32_t*)&lp;
        }
        *(uint4*)(base + l * 16)        = make_uint4(hi[0], hi[1], hi[2], hi[3]);
        *(uint4*)(base + 1024 + l * 16) = make_uint4(lo[0], lo[1], lo[2], lo[3]);
    }
}

__device__ __forceinline__ const unsigned char* ablob8(int t, int c, int s) {
    if (c < 16) return g_xt + (((size_t)(t * 16 + c)) << 13) + s * 2048;
    return g_ht + (((size_t)((t & 1) * 32 + (c - 16))) << 13) + s * 2048;
}
__device__ __forceinline__ void lda(uint4* a, const unsigned char* p, int lane) {
    a[0] = __ldcg((const uint4*)(p + lane * 16));          // hi ks0
    a[1] = __ldcg((const uint4*)(p + 512 + lane * 16));    // hi ks1
    a[2] = __ldcg((const uint4*)(p + 1024 + lane * 16));   // lo ks0
    a[3] = __ldcg((const uint4*)(p + 1536 + lane * 16));   // lo ks1
}

__global__ void __launch_bounds__(kNTHR, 1) lstm8_kernel(
    const float* __restrict__ Wf, const float* __restrict__ bf,
    const float* __restrict__ Wi, const float* __restrict__ bi,
    const float* __restrict__ Wo, const float* __restrict__ bo,
    const float* __restrict__ Wc, const float* __restrict__ bc,
    float* __restrict__ out)
{
    extern __shared__ unsigned char smem[];
    const uint32_t sb = smem_u32_of(smem);
    const int tid = threadIdx.x, lane = tid & 31, w = tid >> 5;
    const int g = w >> 2, s = w & 3;      // k-group (4), m-slice (4)
    const int cta = blockIdx.x, j0 = cta * 8;

    // ---- stage weights bf16 hi/lo SW128 K=64 tiles (once) ----
    {
        const float* const Wp[4] = {Wf, Wi, Wo, Wc};
        for (int r = 0; r < 32; ++r) {
            const float* src = Wp[r & 3] + (size_t)(j0 + (r >> 2)) * 1536;
            for (int kp = tid; kp < 768; kp += kNTHR) {
                int k = kp * 2;
                float f0 = __ldg(src + k), f1 = __ldg(src + k + 1);
                __nv_bfloat16 h0 = __float2bfloat16(f0);
                __nv_bfloat16 h1 = __float2bfloat16(f1);
                __nv_bfloat162 hp; hp.x = h0; hp.y = h1;
                __nv_bfloat162 lp = __floats2bfloat162_rn(
                    f0 - __bfloat162float(h0), f1 - __bfloat162float(h1));
                uint32_t off = swz128((uint32_t)((k >> 6) * 4096 + (r << 7) + ((k & 63) << 1)));
                *(uint32_t*)(smem + WHI + off) = *(uint32_t*)&hp;
                *(uint32_t*)(smem + WLO + off) = *(uint32_t*)&lp;
            }
        }
    }

    // B ldmatrix addressing
    const int rowB = ((lane >> 4) << 3) + (lane & 7);
    const uint32_t bRow = (uint32_t)rowB * 128;
    const int bXor = rowB & 7, bCB = (lane >> 3) & 1;

    // acc staging
    const int m0 = s * 16;
    const int mA = m0 + (lane >> 2), cA = (lane & 3) * 2;
    float* abuf = (float*)(smem + ACC0 + g * ACCSZ);

    // epilogue ownership: thread -> (eb, unit jl)
    const int eb = tid & 63, jl = tid >> 6;      // jl in 0..7
    float bb[4];
    {
        const float* const Bp[4] = {bf, bi, bo, bc};
        #pragma unroll
        for (int q = 0; q < 4; ++q) bb[q] = __ldg(Bp[q] + j0 + jl);
    }
    // h fragment write address pieces (single bf16 element)
    const int colh = (j0 & 31) + jl;
    const int s2 = eb >> 4, ri16 = eb & 15;
    const int lane2 = (ri16 & 7) * 4 + ((colh & 7) >> 1);
    const int r2 = (ri16 >> 3) + 2 * ((colh & 15) >> 3);
    const int ks2 = (colh >> 4) & 1;
    const size_t hoff = (size_t)s2 * 2048 + ks2 * 512 + lane2 * 16 + r2 * 4 + (colh & 1) * 2;
    const size_t hcsel = (size_t)(j0 >> 5) << 13;

    float cs = 0.0f;
    __syncthreads();

    uint4 ap[3][4];
    lda(ap[0], ablob8(0, g, s), lane);        // i=0: c = g        (x)
    lda(ap[1], ablob8(0, 4 + g, s), lane);    // i=1: c = 4 + g    (x)

    for (int t = 0; t < kT; ++t) {
        float acc[4][4];
        #pragma unroll
        for (int nt = 0; nt < 4; ++nt)
            #pragma unroll
            for (int e = 0; e < 4; ++e) acc[nt][e] = 0.0f;

        #pragma unroll 3
        for (int i = 0; i < 12; ++i) {
            // grid barrier: chunks i>=4 are h; first h prefetch is for i=4,
            // issued at iter i=2. Spin (per-warp) right before it, covered by
            // 2 chunks of x compute.
            if (t > 0 && i == 2) spin_on(g_arr + (t - 1), kNCTA);
            if (i < 10)
                lda(ap[(i + 2) % 3], ablob8(t, 4 * (i + 2) + g, s), lane);

            const int c = 4 * i + g;
            const uint32_t bhB = sb + WHI + (uint32_t)(c >> 1) * 4096;
            const int ksg0 = (c & 1) * 2;
            #pragma unroll
            for (int ks = 0; ks < 2; ++ks) {
                uint32_t bh0[4], bh1[4], bl0[4], bl1[4];
                uint32_t cb = (uint32_t)(((2 * (ksg0 + ks) + bCB) ^ bXor) << 4);
                LDSM4(bh0, bhB + bRow + cb);
                LDSM4(bh1, bhB + bRow + cb + 2048);
                LDSM4(bl0, bhB + (WLO - WHI) + bRow + cb);
                LDSM4(bl1, bhB + (WLO - WHI) + bRow + cb + 2048);
                const uint32_t* ah = (const uint32_t*)&ap[i % 3][ks];
                const uint32_t* al = (const uint32_t*)&ap[i % 3][2 + ks];
                MMA16816(acc[0], ah, bh0[0], bh0[1]);
                MMA16816(acc[1], ah, bh0[2], bh0[3]);
                MMA16816(acc[2], ah, bh1[0], bh1[1]);
                MMA16816(acc[3], ah, bh1[2], bh1[3]);
                MMA16816(acc[0], ah, bl0[0], bl0[1]);
                MMA16816(acc[1], ah, bl0[2], bl0[3]);
                MMA16816(acc[2], ah, bl1[0], bl1[1]);
                MMA16816(acc[3], ah, bl1[2], bl1[3]);
                MMA16816(acc[0], al, bh0[0], bh0[1]);
                MMA16816(acc[1], al, bh0[2], bh0[3]);
                MMA16816(acc[2], al, bh1[0], bh1[1]);
                MMA16816(acc[3], al, bh1[2], bh1[3]);
            }
        }

        // prefetch next step's first two x chunks (immutable) during epilogue
        if (t + 1 < kT) {
            lda(ap[0], ablob8(t + 1, g, s), lane);
            lda(ap[1], ablob8(t + 1, 4 + g, s), lane);
        }

        // ---- stage partial D into this k-group's buffer ----
        #pragma unroll
        for (int nt = 0; nt < 4; ++nt) {
            abuf[mA * ACCSTR + nt * 8 + cA]           = acc[nt][0];
            abuf[mA * ACCSTR + nt * 8 + cA + 1]       = acc[nt][1];
            abuf[(mA + 8) * ACCSTR + nt * 8 + cA]     = acc[nt][2];
            abuf[(mA + 8) * ACCSTR + nt * 8 + cA + 1] = acc[nt][3];
        }
        __syncthreads();

        // ---- epilogue: each thread owns (eb, jl) ----
        {
            const float* a0 = (const float*)(smem + ACC0);
            float sum[4];
            #pragma unroll
            for (int q = 0; q < 4; ++q) sum[q] = bb[q];
            #pragma unroll
            for (int bq = 0; bq < 4; ++bq) {
                const float* ab = a0 + bq * (ACCSZ / 4) + eb * ACCSTR + jl * 4;
                #pragma unroll
                for (int q = 0; q < 4; ++q) sum[q] += ab[q];
            }
            float f = sigf(sum[0]), ii = sigf(sum[1]);
            float o = sigf(sum[2]), gg = tanhf(sum[3]);
            float cn = f * cs + ii * gg;
            cs = cn;
            float hv = o * tanhf(cn);

            if (t < kT - 1) {
                __nv_bfloat16 hb = __float2bfloat16(hv);
                unsigned char* dst = g_ht + ((size_t)(((t & 1) ^ 1) * 32) << 13)
                                   + hcsel + hoff;
                *(__nv_bfloat16*)dst          = hb;
                *(__nv_bfloat16*)(dst + 1024) =
                    __float2bfloat16(hv - __bfloat162float(hb));
                __threadfence();
            } else {
                out[eb * kH + j0 + jl]           = hv;
                out[kB * kH + eb * kH + j0 + jl] = cs;
            }
        }
        __syncthreads();
        if (t < kT - 1 && tid == 0) atomicAdd(g_arr + t, 1);
    }
}

extern "C" void kernel_launch(void* const* d_in, const int* in_sizes, int n_in,
                              void* d_out, int out_size)
{
    (void)in_sizes; (void)n_in; (void)out_size;
    const float* x  = (const float*)d_in[0];
    const float* Wf = (const float*)d_in[1];
    const float* bf = (const float*)d_in[2];
    const float* Wi = (const float*)d_in[3];
    const float* bi = (const float*)d_in[4];
    const float* Wo = (const float*)d_in[5];
    const float* bo = (const float*)d_in[6];
    const float* Wc = (const float*)d_in[7];
    const float* bc = (const float*)d_in[8];
    float* out = (float*)d_out;

    cudaFuncSetAttribute(lstm8_kernel,
                         cudaFuncAttributeMaxDynamicSharedMemorySize, SMEMB);
    lstm8_init<<<256, 256>>>();
    lstm8_xsplit<<<kT * 16, 128>>>(x);
    lstm8_kernel<<<kNCTA, kNTHR, SMEMB>>>(Wf, bf, Wi, bi, Wo, bo, Wc, bc, out);
}